// round 11
// baseline (speedup 1.0000x reference)
#include <cuda_runtime.h>
#include <cuda_fp16.h>
#include <cstdint>

#define S_LEN  2048
#define BATCH  2
#define HID    1024
#define DHEAD  64
#define MHEADS 32
#define K_DIM  1024
#define N_DIM  3072
#define M_DIM  4096

// ---------------- scratch (__device__ globals) ----------------
__device__ __half g_hid[(size_t)M_DIM * K_DIM];
__device__ __half g_w  [(size_t)N_DIM * K_DIM];
__device__ __half g_Q  [(size_t)MHEADS * S_LEN * DHEAD];
__device__ __half g_K  [(size_t)MHEADS * S_LEN * DHEAD];
__device__ __half g_V  [(size_t)MHEADS * S_LEN * DHEAD];
__device__ float  g_sq [(size_t)MHEADS * S_LEN];   // pre-scaled by -1/16
__device__ float  g_sk [(size_t)MHEADS * S_LEN];   // pre-scaled by -1/16

// ---------------- helpers ----------------
#define SWZ(o) ((o) ^ (((o) >> 3) & 0x70))

__device__ __forceinline__ uint32_t smem_u32(const void* p) {
    uint32_t a;
    asm("{ .reg .u64 t; cvta.to.shared.u64 t, %1; cvt.u32.u64 %0, t; }" : "=r"(a) : "l"(p));
    return a;
}
__device__ __forceinline__ void ldsm4(uint32_t r[4], uint32_t a) {
    asm volatile("ldmatrix.sync.aligned.m8n8.x4.shared.b16 {%0,%1,%2,%3}, [%4];"
        : "=r"(r[0]), "=r"(r[1]), "=r"(r[2]), "=r"(r[3]) : "r"(a));
}
__device__ __forceinline__ void ldsm4t(uint32_t r[4], uint32_t a) {
    asm volatile("ldmatrix.sync.aligned.m8n8.x4.trans.shared.b16 {%0,%1,%2,%3}, [%4];"
        : "=r"(r[0]), "=r"(r[1]), "=r"(r[2]), "=r"(r[3]) : "r"(a));
}
__device__ __forceinline__ void mma_f16(float c[4], const uint32_t a[4],
                                        uint32_t b0, uint32_t b1) {
    asm volatile("mma.sync.aligned.m16n8k16.row.col.f32.f16.f16.f32 "
        "{%0,%1,%2,%3}, {%4,%5,%6,%7}, {%8,%9}, {%0,%1,%2,%3};"
        : "+f"(c[0]), "+f"(c[1]), "+f"(c[2]), "+f"(c[3])
        : "r"(a[0]), "r"(a[1]), "r"(a[2]), "r"(a[3]), "r"(b0), "r"(b1));
}
__device__ __forceinline__ uint32_t pack_h2(float x, float y) {
    __half2 h = __floats2half2_rn(x, y);
    return *reinterpret_cast<uint32_t*>(&h);
}
#define CP16(dst, src) asm volatile("cp.async.cg.shared.global [%0], [%1], 16;" :: "r"(dst), "l"(src))
#define CP_COMMIT()    asm volatile("cp.async.commit_group;" ::: "memory")
#define CP_WAIT0()     asm volatile("cp.async.wait_group 0;" ::: "memory")

// ---------------- K1: fp32 -> fp16 (both tensors, one launch) ----------------
__global__ __launch_bounds__(256) void convert_kernel(const float* __restrict__ hid_src,
                                                      const float* __restrict__ w_src)
{
    const int n1 = M_DIM * K_DIM / 4;
    const int n2 = N_DIM * K_DIM / 4;
    for (int i = blockIdx.x * blockDim.x + threadIdx.x; i < n1 + n2;
         i += gridDim.x * blockDim.x) {
        if (i < n1) {
            float4 v = ((const float4*)hid_src)[i];
            ((uint2*)g_hid)[i] = make_uint2(pack_h2(v.x, v.y), pack_h2(v.z, v.w));
        } else {
            float4 v = ((const float4*)w_src)[i - n1];
            ((uint2*)g_w)[i - n1] = make_uint2(pack_h2(v.x, v.y), pack_h2(v.z, v.w));
        }
    }
}

// ---------------- K2: QKV GEMM (fp16 HMMA, cp.async double-buffered) -------
#define QST_A 0
#define QST_B 16384
#define QSTG  32768
#define QSMEM 65536

__global__ __launch_bounds__(256, 2) void qkv_hmma(const float* __restrict__ bias)
{
    extern __shared__ char sm[];
    const uint32_t sb = smem_u32(sm);
    const int tid = threadIdx.x, wid = tid >> 5, lane = tid & 31;
    const int n0 = blockIdx.x * 128, m0 = blockIdx.y * 128;
    const int wm = wid >> 1, wn = wid & 1;
    const int lr16 = lane & 15, lk8 = (lane >> 4) << 3;
    const int qr = lane >> 2, qc = (lane & 3) * 2;

    float acc[2][8][4];
    #pragma unroll
    for (int mt = 0; mt < 2; ++mt)
        #pragma unroll
        for (int nt = 0; nt < 8; ++nt)
            #pragma unroll
            for (int c = 0; c < 4; ++c) acc[mt][nt][c] = 0.f;

    {
        const uint32_t stg = sb;
        #pragma unroll
        for (int i = 0; i < 4; ++i) {
            int u = tid + i * 256;
            int row = u >> 3, c16 = u & 7;
            uint32_t so = SWZ((uint32_t)(row * 128 + c16 * 16));
            CP16(stg + QST_A + so, (const char*)(g_hid + (size_t)(m0 + row) * K_DIM + c16 * 8));
            CP16(stg + QST_B + so, (const char*)(g_w   + (size_t)(n0 + row) * K_DIM + c16 * 8));
        }
        CP_COMMIT();
    }

    for (int kc = 0; kc < 16; ++kc) {
        const uint32_t stg = sb + (uint32_t)(kc & 1) * QSTG;
        CP_WAIT0();
        __syncthreads();

        if (kc < 15) {
            const uint32_t nstg = sb + (uint32_t)((kc + 1) & 1) * QSTG;
            const int k0 = (kc + 1) * 64;
            #pragma unroll
            for (int i = 0; i < 4; ++i) {
                int u = tid + i * 256;
                int row = u >> 3, c16 = u & 7;
                uint32_t so = SWZ((uint32_t)(row * 128 + c16 * 16));
                CP16(nstg + QST_A + so, (const char*)(g_hid + (size_t)(m0 + row) * K_DIM + k0 + c16 * 8));
                CP16(nstg + QST_B + so, (const char*)(g_w   + (size_t)(n0 + row) * K_DIM + k0 + c16 * 8));
            }
            CP_COMMIT();
        }

        #pragma unroll
        for (int ks = 0; ks < 4; ++ks) {
            const uint32_t kb = (ks * 16 + lk8) * 2;
            uint32_t a[2][4];
            #pragma unroll
            for (int mt = 0; mt < 2; ++mt) {
                uint32_t byte = (wm * 32 + mt * 16 + lr16) * 128 + kb;
                ldsm4(a[mt], stg + QST_A + SWZ(byte));
            }
            #pragma unroll
            for (int np = 0; np < 4; ++np) {
                uint32_t byte = (wn * 64 + np * 16 + lr16) * 128 + kb;
                uint32_t b[4];
                ldsm4(b, stg + QST_B + SWZ(byte));
                #pragma unroll
                for (int h = 0; h < 2; ++h)
                    #pragma unroll
                    for (int mt = 0; mt < 2; ++mt)
                        mma_f16(acc[mt][np * 2 + h], a[mt], b[h], b[h + 2]);
            }
        }
    }

    // epilogue
    const int nbase = n0 + wn * 64;
    const int head = nbase / 192;
    const int wsel = nbase - head * 192;
    const int sel = wsel >> 6;

    #pragma unroll
    for (int mt = 0; mt < 2; ++mt) {
        const int rA = m0 + wm * 32 + mt * 16 + qr;
        const int rB = rA + 8;
        const int sA = rA >> 1, mhA = (rA & 1) * 16 + head;
        const int sB = rB >> 1, mhB = (rB & 1) * 16 + head;
        const size_t offA = ((size_t)mhA * S_LEN + sA) * DHEAD;
        const size_t offB = ((size_t)mhB * S_LEN + sB) * DHEAD;
        if (sel == 2) {
            #pragma unroll
            for (int nt = 0; nt < 8; ++nt) {
                const float* c = acc[mt][nt];
                const int n = nbase + nt * 8 + qc;
                float b0 = __ldg(bias + n), b1 = __ldg(bias + n + 1);
                int d = nt * 8 + qc;
                *(uint32_t*)(g_V + offA + d) = pack_h2(c[0] + b0, c[1] + b1);
                *(uint32_t*)(g_V + offB + d) = pack_h2(c[2] + b0, c[3] + b1);
            }
        } else {
            __half* oh = sel ? g_K : g_Q;
            float sumA = 0.f, sumB = 0.f;
            #pragma unroll
            for (int nt = 0; nt < 8; ++nt) {
                const float* c = acc[mt][nt];
                const int n = nbase + nt * 8 + qc;
                float b0 = __ldg(bias + n), b1 = __ldg(bias + n + 1);
                float v00 = c[0] + b0, v01 = c[1] + b1;
                float v10 = c[2] + b0, v11 = c[3] + b1;
                sumA = fmaf(v00, v00, fmaf(v01, v01, sumA));
                sumB = fmaf(v10, v10, fmaf(v11, v11, sumB));
                int d = nt * 8 + qc;
                *(uint32_t*)(oh + offA + d) = pack_h2(v00, v01);
                *(uint32_t*)(oh + offB + d) = pack_h2(v10, v11);
            }
            sumA += __shfl_xor_sync(0xffffffffu, sumA, 1);
            sumA += __shfl_xor_sync(0xffffffffu, sumA, 2);
            sumB += __shfl_xor_sync(0xffffffffu, sumB, 1);
            sumB += __shfl_xor_sync(0xffffffffu, sumB, 2);
            if ((lane & 3) == 0) {
                float* dst = sel ? g_sk : g_sq;
                dst[(size_t)mhA * S_LEN + sA] = sumA * -0.0625f;   // pre-scaled
                dst[(size_t)mhB * S_LEN + sB] = sumB * -0.0625f;   // pre-scaled
            }
        }
    }
}

// ---------------- K3: attention (4 warps x 32 rows, 32-key halves) ---------
// Per half: GEMM1-half -> epilogue-half -> GEMM2-half, each a contiguous
// volatile-asm block (no stores inside MMA regions). Live regs ~165 -> 3 CTAs.
#define A_Q   0
#define A_STG 16384
#define STG_SZ 16640
#define ST_K  0
#define ST_V  8192
#define ST_SK 16384
#define ASMEM (A_STG + 2 * STG_SZ)   // 49664

__global__ __launch_bounds__(128, 3) void attn_hmma(float* __restrict__ ctx_out,
                                                    float* __restrict__ score_out)
{
    extern __shared__ char sm[];
    const uint32_t sb = smem_u32(sm);
    const int tid = threadIdx.x, wid = tid >> 5, lane = tid & 31;
    const int m = blockIdx.y, q0 = blockIdx.x * 128;
    const int lr16 = lane & 15, lk8 = (lane >> 4) << 3;
    const int qr = lane >> 2, qc = (lane & 3) * 2;
    const int row0 = wid * 32;

    // stage Q tile + stage 0 of K/V
    #pragma unroll
    for (int i = 0; i < 8; ++i) {
        int u = tid + i * 128;
        int row = u >> 3, c16 = u & 7;
        uint32_t so = SWZ((uint32_t)(row * 128 + c16 * 16));
        CP16(sb + A_Q + so, (const char*)(g_Q + ((size_t)m * S_LEN + q0 + row) * DHEAD + c16 * 8));
    }
    {
        const uint32_t stg = sb + A_STG;
        #pragma unroll
        for (int i = 0; i < 4; ++i) {
            int u = tid + i * 128;
            int row = u >> 3, c16 = u & 7;
            uint32_t so = SWZ((uint32_t)(row * 128 + c16 * 16));
            size_t goff = ((size_t)m * S_LEN + row) * DHEAD + c16 * 8;
            CP16(stg + ST_K + so, (const char*)(g_K + goff));
            CP16(stg + ST_V + so, (const char*)(g_V + goff));
        }
        if (tid < 16) CP16(stg + ST_SK + tid * 16,
                           (const char*)(g_sk + (size_t)m * S_LEN) + tid * 16);
        CP_COMMIT();
    }
    CP_WAIT0();
    __syncthreads();

    // persistent Q fragments: 2 row-groups x 4 k16 chunks
    uint32_t qf[2][4][4];
    #pragma unroll
    for (int g = 0; g < 2; ++g)
        #pragma unroll
        for (int ks = 0; ks < 4; ++ks) {
            uint32_t byte = (row0 + g * 16 + lr16) * 128 + (ks * 16 + lk8) * 2;
            ldsm4(qf[g][ks], sb + A_Q + SWZ(byte));
        }

    float sqv[2][2];   // pre-scaled by -1/16
    #pragma unroll
    for (int g = 0; g < 2; ++g) {
        sqv[g][0] = g_sq[(size_t)m * S_LEN + q0 + row0 + g * 16 + qr];
        sqv[g][1] = g_sq[(size_t)m * S_LEN + q0 + row0 + g * 16 + qr + 8];
    }

    float ctx[2][8][4];
    #pragma unroll
    for (int g = 0; g < 2; ++g)
        #pragma unroll
        for (int nt = 0; nt < 8; ++nt)
            #pragma unroll
            for (int c = 0; c < 4; ++c) ctx[g][nt][c] = 0.f;

    for (int t = 0; t < 32; ++t) {
        const int t0 = t * 64;
        const uint32_t stg = sb + A_STG + (uint32_t)(t & 1) * STG_SZ;

        if (t > 0) { CP_WAIT0(); __syncthreads(); }

        if (t < 31) {      // prefetch stage t+1
            const uint32_t nstg = sb + A_STG + (uint32_t)((t + 1) & 1) * STG_SZ;
            const int n0r = t0 + 64;
            #pragma unroll
            for (int i = 0; i < 4; ++i) {
                int u = tid + i * 128;
                int row = u >> 3, c16 = u & 7;
                uint32_t so = SWZ((uint32_t)(row * 128 + c16 * 16));
                size_t goff = ((size_t)m * S_LEN + n0r + row) * DHEAD + c16 * 8;
                CP16(nstg + ST_K + so, (const char*)(g_K + goff));
                CP16(nstg + ST_V + so, (const char*)(g_V + goff));
            }
            if (tid < 16) CP16(nstg + ST_SK + tid * 16,
                               (const char*)(g_sk + (size_t)m * S_LEN + n0r) + tid * 16);
            CP_COMMIT();
        }

        const float* skp = (const float*)(sm + A_STG + (t & 1) * STG_SZ + ST_SK);

        #pragma unroll
        for (int half = 0; half < 2; ++half) {
            const int koff = half * 32;

            // ---- GEMM1-half: S(32x32) = Q·K^T (contiguous MMA block) ----
            float sacc[2][4][4];
            #pragma unroll
            for (int g = 0; g < 2; ++g)
                #pragma unroll
                for (int nt = 0; nt < 4; ++nt)
                    #pragma unroll
                    for (int c = 0; c < 4; ++c) sacc[g][nt][c] = 0.f;

            #pragma unroll
            for (int ks = 0; ks < 4; ++ks) {
                const uint32_t kb = (ks * 16 + lk8) * 2;
                #pragma unroll
                for (int nb = 0; nb < 2; ++nb) {
                    uint32_t byte = (koff + nb * 16 + lr16) * 128 + kb;
                    uint32_t b[4];
                    ldsm4(b, stg + ST_K + SWZ(byte));
                    #pragma unroll
                    for (int h = 0; h < 2; ++h)
                        #pragma unroll
                        for (int g = 0; g < 2; ++g)
                            mma_f16(sacc[g][nb * 2 + h], qf[g][ks], b[h], b[h + 2]);
                }
            }

            // ---- epilogue-half: scores + exp -> P frags (contiguous) ----
            uint32_t pa[2][2][4];
            #pragma unroll
            for (int g = 0; g < 2; ++g) {
                float* srowA = score_out + ((size_t)m * S_LEN + q0 + row0 + g * 16 + qr) * S_LEN + t0 + koff;
                float* srowB = srowA + 8 * S_LEN;
                #pragma unroll
                for (int nt = 0; nt < 4; ++nt) {
                    const float* c = sacc[g][nt];
                    const int cg = nt * 8 + qc;
                    float2 kv = *(const float2*)(skp + koff + cg);   // pre-scaled
                    float b0x = sqv[g][0] + kv.x, b0y = sqv[g][0] + kv.y;
                    float b1x = sqv[g][1] + kv.x, b1y = sqv[g][1] + kv.y;
                    float s00 = fmaf(c[0], 0.125f, b0x);
                    float s01 = fmaf(c[1], 0.125f, b0y);
                    float s10 = fmaf(c[2], 0.125f, b1x);
                    float s11 = fmaf(c[3], 0.125f, b1y);
                    *(float2*)(srowA + cg) = make_float2(s00, s01);
                    *(float2*)(srowB + cg) = make_float2(s10, s11);
                    pa[g][nt >> 1][(nt & 1) * 2 + 0] = pack_h2(__expf(s00), __expf(s01));
                    pa[g][nt >> 1][(nt & 1) * 2 + 1] = pack_h2(__expf(s10), __expf(s11));
                }
            }

            // ---- GEMM2-half: ctx += P·V (contiguous MMA block) ----
            #pragma unroll
            for (int kc = 0; kc < 2; ++kc) {
                const int kt = koff + kc * 16 + (lane & 7) + lk8;
                #pragma unroll
                for (int nd = 0; nd < 4; ++nd) {
                    const int nb = nd * 16 + (lane & 8);
                    uint32_t byte = kt * 128 + nb * 2;
                    uint32_t vh[4];
                    ldsm4t(vh, stg + ST_V + SWZ(byte));
                    #pragma unroll
                    for (int h = 0; h < 2; ++h)
                        #pragma unroll
                        for (int g = 0; g < 2; ++g)
                            mma_f16(ctx[g][nd * 2 + h], pa[g][kc], vh[h], vh[h + 2]);
                }
            }
        }
    }

    // ---- write ctx ----
    const int bb = m >> 4, hh = m & 15;
    #pragma unroll
    for (int g = 0; g < 2; ++g) {
        const int rl = row0 + g * 16 + qr;
        float* dA = ctx_out + ((size_t)(q0 + rl) * BATCH + bb) * HID + hh * 64;
        float* dB = ctx_out + ((size_t)(q0 + rl + 8) * BATCH + bb) * HID + hh * 64;
        #pragma unroll
        for (int nt = 0; nt < 8; ++nt) {
            const float* c = ctx[g][nt];
            const int d = nt * 8 + qc;
            *(float2*)(dA + d) = make_float2(c[0], c[1]);
            *(float2*)(dB + d) = make_float2(c[2], c[3]);
        }
    }
}

// ---------------------------------------------------------------------------
extern "C" void kernel_launch(void* const* d_in, const int* in_sizes, int n_in,
                              void* d_out, int out_size)
{
    const float* hidden = (const float*)d_in[0];
    const float* W      = (const float*)d_in[1];
    const float* bias   = (const float*)d_in[2];
    float* ctx_out   = (float*)d_out;
    float* score_out = ctx_out + (size_t)S_LEN * BATCH * HID;

    convert_kernel<<<2048, 256>>>(hidden, W);

    cudaFuncSetAttribute(qkv_hmma, cudaFuncAttributeMaxDynamicSharedMemorySize, QSMEM);
    dim3 g1(N_DIM / 128, M_DIM / 128);
    qkv_hmma<<<g1, 256, QSMEM>>>(bias);

    cudaFuncSetAttribute(attn_hmma, cudaFuncAttributeMaxDynamicSharedMemorySize, ASMEM);
    dim3 g2(S_LEN / 128, MHEADS);
    attn_hmma<<<g2, 128, ASMEM>>>(ctx_out, score_out);
}

// round 12
// speedup vs baseline: 1.2076x; 1.2076x over previous
#include <cuda_runtime.h>
#include <cuda_fp16.h>
#include <cstdint>

#define S_LEN  2048
#define BATCH  2
#define HID    1024
#define DHEAD  64
#define MHEADS 32
#define K_DIM  1024
#define N_DIM  3072
#define M_DIM  4096

// ---------------- scratch (__device__ globals) ----------------
__device__ __half g_hid[(size_t)M_DIM * K_DIM];
__device__ __half g_w  [(size_t)N_DIM * K_DIM];
__device__ __half g_Q  [(size_t)MHEADS * S_LEN * DHEAD];
__device__ __half g_K  [(size_t)MHEADS * S_LEN * DHEAD];
__device__ __half g_V  [(size_t)MHEADS * S_LEN * DHEAD];
__device__ float  g_sq [(size_t)MHEADS * S_LEN];   // pre-scaled by -1/16
__device__ float  g_sk [(size_t)MHEADS * S_LEN];   // pre-scaled by -1/16

// ---------------- helpers ----------------
#define SWZ(o) ((o) ^ (((o) >> 3) & 0x70))

__device__ __forceinline__ uint32_t smem_u32(const void* p) {
    uint32_t a;
    asm("{ .reg .u64 t; cvta.to.shared.u64 t, %1; cvt.u32.u64 %0, t; }" : "=r"(a) : "l"(p));
    return a;
}
__device__ __forceinline__ void ldsm4(uint32_t r[4], uint32_t a) {
    asm volatile("ldmatrix.sync.aligned.m8n8.x4.shared.b16 {%0,%1,%2,%3}, [%4];"
        : "=r"(r[0]), "=r"(r[1]), "=r"(r[2]), "=r"(r[3]) : "r"(a));
}
__device__ __forceinline__ void ldsm4t(uint32_t r[4], uint32_t a) {
    asm volatile("ldmatrix.sync.aligned.m8n8.x4.trans.shared.b16 {%0,%1,%2,%3}, [%4];"
        : "=r"(r[0]), "=r"(r[1]), "=r"(r[2]), "=r"(r[3]) : "r"(a));
}
__device__ __forceinline__ void mma_f16(float c[4], const uint32_t a[4],
                                        uint32_t b0, uint32_t b1) {
    asm volatile("mma.sync.aligned.m16n8k16.row.col.f32.f16.f16.f32 "
        "{%0,%1,%2,%3}, {%4,%5,%6,%7}, {%8,%9}, {%0,%1,%2,%3};"
        : "+f"(c[0]), "+f"(c[1]), "+f"(c[2]), "+f"(c[3])
        : "r"(a[0]), "r"(a[1]), "r"(a[2]), "r"(a[3]), "r"(b0), "r"(b1));
}
__device__ __forceinline__ uint32_t pack_h2(float x, float y) {
    __half2 h = __floats2half2_rn(x, y);
    return *reinterpret_cast<uint32_t*>(&h);
}
#define CP16(dst, src) asm volatile("cp.async.cg.shared.global [%0], [%1], 16;" :: "r"(dst), "l"(src))
#define CP_COMMIT()    asm volatile("cp.async.commit_group;" ::: "memory")
#define CP_WAIT0()     asm volatile("cp.async.wait_group 0;" ::: "memory")

// ---------------- K1: fp32 -> fp16 (both tensors, one launch) ----------------
__global__ __launch_bounds__(256) void convert_kernel(const float* __restrict__ hid_src,
                                                      const float* __restrict__ w_src)
{
    const int n1 = M_DIM * K_DIM / 4;
    const int n2 = N_DIM * K_DIM / 4;
    for (int i = blockIdx.x * blockDim.x + threadIdx.x; i < n1 + n2;
         i += gridDim.x * blockDim.x) {
        if (i < n1) {
            float4 v = ((const float4*)hid_src)[i];
            ((uint2*)g_hid)[i] = make_uint2(pack_h2(v.x, v.y), pack_h2(v.z, v.w));
        } else {
            float4 v = ((const float4*)w_src)[i - n1];
            ((uint2*)g_w)[i - n1] = make_uint2(pack_h2(v.x, v.y), pack_h2(v.z, v.w));
        }
    }
}

// ---------------- K2: QKV GEMM (fp16 HMMA, cp.async double-buffered) -------
#define QST_A 0
#define QST_B 16384
#define QSTG  32768
#define QSMEM 65536

__global__ __launch_bounds__(256, 2) void qkv_hmma(const float* __restrict__ bias)
{
    extern __shared__ char sm[];
    const uint32_t sb = smem_u32(sm);
    const int tid = threadIdx.x, wid = tid >> 5, lane = tid & 31;
    const int n0 = blockIdx.x * 128, m0 = blockIdx.y * 128;
    const int wm = wid >> 1, wn = wid & 1;
    const int lr16 = lane & 15, lk8 = (lane >> 4) << 3;
    const int qr = lane >> 2, qc = (lane & 3) * 2;

    float acc[2][8][4];
    #pragma unroll
    for (int mt = 0; mt < 2; ++mt)
        #pragma unroll
        for (int nt = 0; nt < 8; ++nt)
            #pragma unroll
            for (int c = 0; c < 4; ++c) acc[mt][nt][c] = 0.f;

    {
        const uint32_t stg = sb;
        #pragma unroll
        for (int i = 0; i < 4; ++i) {
            int u = tid + i * 256;
            int row = u >> 3, c16 = u & 7;
            uint32_t so = SWZ((uint32_t)(row * 128 + c16 * 16));
            CP16(stg + QST_A + so, (const char*)(g_hid + (size_t)(m0 + row) * K_DIM + c16 * 8));
            CP16(stg + QST_B + so, (const char*)(g_w   + (size_t)(n0 + row) * K_DIM + c16 * 8));
        }
        CP_COMMIT();
    }

    for (int kc = 0; kc < 16; ++kc) {
        const uint32_t stg = sb + (uint32_t)(kc & 1) * QSTG;
        CP_WAIT0();
        __syncthreads();

        if (kc < 15) {
            const uint32_t nstg = sb + (uint32_t)((kc + 1) & 1) * QSTG;
            const int k0 = (kc + 1) * 64;
            #pragma unroll
            for (int i = 0; i < 4; ++i) {
                int u = tid + i * 256;
                int row = u >> 3, c16 = u & 7;
                uint32_t so = SWZ((uint32_t)(row * 128 + c16 * 16));
                CP16(nstg + QST_A + so, (const char*)(g_hid + (size_t)(m0 + row) * K_DIM + k0 + c16 * 8));
                CP16(nstg + QST_B + so, (const char*)(g_w   + (size_t)(n0 + row) * K_DIM + k0 + c16 * 8));
            }
            CP_COMMIT();
        }

        #pragma unroll
        for (int ks = 0; ks < 4; ++ks) {
            const uint32_t kb = (ks * 16 + lk8) * 2;
            uint32_t a[2][4];
            #pragma unroll
            for (int mt = 0; mt < 2; ++mt) {
                uint32_t byte = (wm * 32 + mt * 16 + lr16) * 128 + kb;
                ldsm4(a[mt], stg + QST_A + SWZ(byte));
            }
            #pragma unroll
            for (int np = 0; np < 4; ++np) {
                uint32_t byte = (wn * 64 + np * 16 + lr16) * 128 + kb;
                uint32_t b[4];
                ldsm4(b, stg + QST_B + SWZ(byte));
                #pragma unroll
                for (int h = 0; h < 2; ++h)
                    #pragma unroll
                    for (int mt = 0; mt < 2; ++mt)
                        mma_f16(acc[mt][np * 2 + h], a[mt], b[h], b[h + 2]);
            }
        }
    }

    // epilogue
    const int nbase = n0 + wn * 64;
    const int head = nbase / 192;
    const int wsel = nbase - head * 192;
    const int sel = wsel >> 6;

    #pragma unroll
    for (int mt = 0; mt < 2; ++mt) {
        const int rA = m0 + wm * 32 + mt * 16 + qr;
        const int rB = rA + 8;
        const int sA = rA >> 1, mhA = (rA & 1) * 16 + head;
        const int sB = rB >> 1, mhB = (rB & 1) * 16 + head;
        const size_t offA = ((size_t)mhA * S_LEN + sA) * DHEAD;
        const size_t offB = ((size_t)mhB * S_LEN + sB) * DHEAD;
        if (sel == 2) {
            #pragma unroll
            for (int nt = 0; nt < 8; ++nt) {
                const float* c = acc[mt][nt];
                const int n = nbase + nt * 8 + qc;
                float b0 = __ldg(bias + n), b1 = __ldg(bias + n + 1);
                int d = nt * 8 + qc;
                *(uint32_t*)(g_V + offA + d) = pack_h2(c[0] + b0, c[1] + b1);
                *(uint32_t*)(g_V + offB + d) = pack_h2(c[2] + b0, c[3] + b1);
            }
        } else {
            __half* oh = sel ? g_K : g_Q;
            float sumA = 0.f, sumB = 0.f;
            #pragma unroll
            for (int nt = 0; nt < 8; ++nt) {
                const float* c = acc[mt][nt];
                const int n = nbase + nt * 8 + qc;
                float b0 = __ldg(bias + n), b1 = __ldg(bias + n + 1);
                float v00 = c[0] + b0, v01 = c[1] + b1;
                float v10 = c[2] + b0, v11 = c[3] + b1;
                sumA = fmaf(v00, v00, fmaf(v01, v01, sumA));
                sumB = fmaf(v10, v10, fmaf(v11, v11, sumB));
                int d = nt * 8 + qc;
                *(uint32_t*)(oh + offA + d) = pack_h2(v00, v01);
                *(uint32_t*)(oh + offB + d) = pack_h2(v10, v11);
            }
            sumA += __shfl_xor_sync(0xffffffffu, sumA, 1);
            sumA += __shfl_xor_sync(0xffffffffu, sumA, 2);
            sumB += __shfl_xor_sync(0xffffffffu, sumB, 1);
            sumB += __shfl_xor_sync(0xffffffffu, sumB, 2);
            if ((lane & 3) == 0) {
                float* dst = sel ? g_sk : g_sq;
                dst[(size_t)mhA * S_LEN + sA] = sumA * -0.0625f;   // pre-scaled
                dst[(size_t)mhB * S_LEN + sB] = sumB * -0.0625f;   // pre-scaled
            }
        }
    }
}

// ---------------- K3: attention (R10 structure + streaming stores) ---------
// 4 warps x 32 rows; GEMM1 (full 64 keys) -> epilogue -> GEMM2, contiguous
// volatile-asm blocks. Score/ctx writes use __stcs (write-once data, keep
// the 537 MB stream out of L2 to protect K/V reuse).
#define A_Q   0
#define A_STG 16384
#define STG_SZ 16640
#define ST_K  0
#define ST_V  8192
#define ST_SK 16384
#define ASMEM (A_STG + 2 * STG_SZ)   // 49664

__global__ __launch_bounds__(128, 2) void attn_hmma(float* __restrict__ ctx_out,
                                                    float* __restrict__ score_out)
{
    extern __shared__ char sm[];
    const uint32_t sb = smem_u32(sm);
    const int tid = threadIdx.x, wid = tid >> 5, lane = tid & 31;
    const int m = blockIdx.y, q0 = blockIdx.x * 128;
    const int lr16 = lane & 15, lk8 = (lane >> 4) << 3;
    const int qr = lane >> 2, qc = (lane & 3) * 2;
    const int row0 = wid * 32;

    // stage Q tile + stage 0 of K/V
    #pragma unroll
    for (int i = 0; i < 8; ++i) {
        int u = tid + i * 128;
        int row = u >> 3, c16 = u & 7;
        uint32_t so = SWZ((uint32_t)(row * 128 + c16 * 16));
        CP16(sb + A_Q + so, (const char*)(g_Q + ((size_t)m * S_LEN + q0 + row) * DHEAD + c16 * 8));
    }
    {
        const uint32_t stg = sb + A_STG;
        #pragma unroll
        for (int i = 0; i < 4; ++i) {
            int u = tid + i * 128;
            int row = u >> 3, c16 = u & 7;
            uint32_t so = SWZ((uint32_t)(row * 128 + c16 * 16));
            size_t goff = ((size_t)m * S_LEN + row) * DHEAD + c16 * 8;
            CP16(stg + ST_K + so, (const char*)(g_K + goff));
            CP16(stg + ST_V + so, (const char*)(g_V + goff));
        }
        if (tid < 16) CP16(stg + ST_SK + tid * 16,
                           (const char*)(g_sk + (size_t)m * S_LEN) + tid * 16);
        CP_COMMIT();
    }
    CP_WAIT0();
    __syncthreads();

    // persistent Q fragments: 2 row-groups x 4 k16 chunks
    uint32_t qf[2][4][4];
    #pragma unroll
    for (int g = 0; g < 2; ++g)
        #pragma unroll
        for (int ks = 0; ks < 4; ++ks) {
            uint32_t byte = (row0 + g * 16 + lr16) * 128 + (ks * 16 + lk8) * 2;
            ldsm4(qf[g][ks], sb + A_Q + SWZ(byte));
        }

    float sqv[2][2];   // pre-scaled by -1/16
    #pragma unroll
    for (int g = 0; g < 2; ++g) {
        sqv[g][0] = g_sq[(size_t)m * S_LEN + q0 + row0 + g * 16 + qr];
        sqv[g][1] = g_sq[(size_t)m * S_LEN + q0 + row0 + g * 16 + qr + 8];
    }

    float ctx[2][8][4];
    #pragma unroll
    for (int g = 0; g < 2; ++g)
        #pragma unroll
        for (int nt = 0; nt < 8; ++nt)
            #pragma unroll
            for (int c = 0; c < 4; ++c) ctx[g][nt][c] = 0.f;

    for (int t = 0; t < 32; ++t) {
        const int t0 = t * 64;
        const uint32_t stg = sb + A_STG + (uint32_t)(t & 1) * STG_SZ;

        if (t > 0) { CP_WAIT0(); __syncthreads(); }

        if (t < 31) {      // prefetch stage t+1
            const uint32_t nstg = sb + A_STG + (uint32_t)((t + 1) & 1) * STG_SZ;
            const int n0r = t0 + 64;
            #pragma unroll
            for (int i = 0; i < 4; ++i) {
                int u = tid + i * 128;
                int row = u >> 3, c16 = u & 7;
                uint32_t so = SWZ((uint32_t)(row * 128 + c16 * 16));
                size_t goff = ((size_t)m * S_LEN + n0r + row) * DHEAD + c16 * 8;
                CP16(nstg + ST_K + so, (const char*)(g_K + goff));
                CP16(nstg + ST_V + so, (const char*)(g_V + goff));
            }
            if (tid < 16) CP16(nstg + ST_SK + tid * 16,
                               (const char*)(g_sk + (size_t)m * S_LEN + n0r) + tid * 16);
            CP_COMMIT();
        }

        // ---- GEMM1: S(32x64) = Q·K^T ----
        float sacc[2][8][4];
        #pragma unroll
        for (int g = 0; g < 2; ++g)
            #pragma unroll
            for (int nt = 0; nt < 8; ++nt)
                #pragma unroll
                for (int c = 0; c < 4; ++c) sacc[g][nt][c] = 0.f;

        #pragma unroll
        for (int ks = 0; ks < 4; ++ks) {
            const uint32_t kb = (ks * 16 + lk8) * 2;
            #pragma unroll
            for (int nb = 0; nb < 4; ++nb) {
                uint32_t byte = (nb * 16 + lr16) * 128 + kb;
                uint32_t b[4];
                ldsm4(b, stg + ST_K + SWZ(byte));
                #pragma unroll
                for (int h = 0; h < 2; ++h)
                    #pragma unroll
                    for (int g = 0; g < 2; ++g)
                        mma_f16(sacc[g][nb * 2 + h], qf[g][ks], b[h], b[h + 2]);
            }
        }

        // ---- scores + exp -> P fragments in registers ----
        const float* skp = (const float*)(sm + A_STG + (t & 1) * STG_SZ + ST_SK);
        uint32_t pa[2][4][4];
        #pragma unroll
        for (int g = 0; g < 2; ++g) {
            float* srowA = score_out + ((size_t)m * S_LEN + q0 + row0 + g * 16 + qr) * S_LEN + t0;
            float* srowB = srowA + 8 * S_LEN;
            #pragma unroll
            for (int nt = 0; nt < 8; ++nt) {
                const float* c = sacc[g][nt];
                const int cg = nt * 8 + qc;
                float2 kv = *(const float2*)(skp + cg);   // pre-scaled -sk/16
                float b0x = sqv[g][0] + kv.x, b0y = sqv[g][0] + kv.y;
                float b1x = sqv[g][1] + kv.x, b1y = sqv[g][1] + kv.y;
                float s00 = fmaf(c[0], 0.125f, b0x);
                float s01 = fmaf(c[1], 0.125f, b0y);
                float s10 = fmaf(c[2], 0.125f, b1x);
                float s11 = fmaf(c[3], 0.125f, b1y);
                __stcs((float2*)(srowA + cg), make_float2(s00, s01));
                __stcs((float2*)(srowB + cg), make_float2(s10, s11));
                pa[g][nt >> 1][(nt & 1) * 2 + 0] = pack_h2(__expf(s00), __expf(s01));
                pa[g][nt >> 1][(nt & 1) * 2 + 1] = pack_h2(__expf(s10), __expf(s11));
            }
        }

        // ---- GEMM2: ctx(32x64) += P·V ----
        #pragma unroll
        for (int kc = 0; kc < 4; ++kc) {
            const int kt = kc * 16 + (lane & 7) + lk8;
            #pragma unroll
            for (int nd = 0; nd < 4; ++nd) {
                const int nb = nd * 16 + (lane & 8);
                uint32_t byte = kt * 128 + nb * 2;
                uint32_t vh[4];
                ldsm4t(vh, stg + ST_V + SWZ(byte));
                #pragma unroll
                for (int h = 0; h < 2; ++h)
                    #pragma unroll
                    for (int g = 0; g < 2; ++g)
                        mma_f16(ctx[g][nd * 2 + h], pa[g][kc], vh[h], vh[h + 2]);
            }
        }
    }

    // ---- write ctx (streaming) ----
    const int bb = m >> 4, hh = m & 15;
    #pragma unroll
    for (int g = 0; g < 2; ++g) {
        const int rl = row0 + g * 16 + qr;
        float* dA = ctx_out + ((size_t)(q0 + rl) * BATCH + bb) * HID + hh * 64;
        float* dB = ctx_out + ((size_t)(q0 + rl + 8) * BATCH + bb) * HID + hh * 64;
        #pragma unroll
        for (int nt = 0; nt < 8; ++nt) {
            const float* c = ctx[g][nt];
            const int d = nt * 8 + qc;
            __stcs((float2*)(dA + d), make_float2(c[0], c[1]));
            __stcs((float2*)(dB + d), make_float2(c[2], c[3]));
        }
    }
}

// ---------------------------------------------------------------------------
extern "C" void kernel_launch(void* const* d_in, const int* in_sizes, int n_in,
                              void* d_out, int out_size)
{
    const float* hidden = (const float*)d_in[0];
    const float* W      = (const float*)d_in[1];
    const float* bias   = (const float*)d_in[2];
    float* ctx_out   = (float*)d_out;
    float* score_out = ctx_out + (size_t)S_LEN * BATCH * HID;

    convert_kernel<<<2048, 256>>>(hidden, W);

    cudaFuncSetAttribute(qkv_hmma, cudaFuncAttributeMaxDynamicSharedMemorySize, QSMEM);
    dim3 g1(N_DIM / 128, M_DIM / 128);
    qkv_hmma<<<g1, 256, QSMEM>>>(bias);

    cudaFuncSetAttribute(attn_hmma, cudaFuncAttributeMaxDynamicSharedMemorySize, ASMEM);
    dim3 g2(S_LEN / 128, MHEADS);
    attn_hmma<<<g2, 128, ASMEM>>>(ctx_out, score_out);
}